// round 8
// baseline (speedup 1.0000x reference)
#include <cuda_runtime.h>

#define FULL 0xffffffffu

static constexpr int B_ = 64;
static constexpr int S_ = 12;
static constexpr int N_ = 207;
static constexpr int F_ = 2;
static constexpr int NCIRC = B_ * N_;       // 13248
static constexpr int CPB = 16;              // circuits per 256-thread block
static constexpr float PI_F = 3.14159265358979323846f;

// Each warp-PAIR handles 4 circuits: even warp = re component, odd warp = im.
// Within a warp: 4 groups of 8 lanes, one circuit per group.
// Flat j (8 bits) = (g << 5) | r;  g = lane & 7, r = reg idx (5 bits).
// qubit -> j-bit: q0->7 q5->6 q7->5 (lane g bits 2,1,0)
//                 q1->4 q2->3 q3->2 q4->1 q6->0 (reg bits 4..0)

__device__ __forceinline__ float shx(float v, int m) { return __shfl_xor_sync(FULL, v, m); }

// ---- RY on a register bit P (single component) ----
template<int P>
__device__ __forceinline__ void ry_reg(float (&st)[32], float c, float s) {
    constexpr int m = 1 << P;
    #pragma unroll
    for (int r = 0; r < 32; ++r) if (!(r & m)) {
        const int r1 = r | m;
        float a0 = st[r], a1 = st[r1];
        st[r]  = fmaf(c, a0, -s * a1);
        st[r1] = fmaf(s, a0,  c * a1);
    }
}

// ---- RY on a lane bit LB ----
template<int LB>
__device__ __forceinline__ void ry_lane(float (&st)[32], float c, float s, int lane) {
    constexpr int L = 1 << LB;
    const float sg = ((lane >> LB) & 1) ? s : -s;
    #pragma unroll
    for (int r = 0; r < 32; ++r) {
        float p = shx(st[r], L);
        st[r] = fmaf(c, st[r], sg * p);
    }
}

// ---- fused conv pair, both qubits reg bits (PA first, PB second) ----
template<int PA, int PB>
__device__ __forceinline__ void conv_rr(float (&st)[32], const float4* __restrict__ U4) {
    const float4 a0 = U4[0], a1 = U4[1], a2 = U4[2], a3 = U4[3];
    constexpr int ma = 1 << PA, mb = 1 << PB;
    #pragma unroll
    for (int r0 = 0; r0 < 32; ++r0) if (!(r0 & (ma | mb))) {
        const int i1 = r0 | mb, i2 = r0 | ma, i3 = r0 | ma | mb;
        float v0 = st[r0], v1 = st[i1], v2 = st[i2], v3 = st[i3];
        st[r0] = fmaf(a0.x, v0, fmaf(a0.y, v1, fmaf(a0.z, v2, a0.w * v3)));
        st[i1] = fmaf(a1.x, v0, fmaf(a1.y, v1, fmaf(a1.z, v2, a1.w * v3)));
        st[i2] = fmaf(a2.x, v0, fmaf(a2.y, v1, fmaf(a2.z, v2, a2.w * v3)));
        st[i3] = fmaf(a3.x, v0, fmaf(a3.y, v1, fmaf(a3.z, v2, a3.w * v3)));
    }
}

// ---- fused conv pair, one qubit on lane bit LBIT, one on reg bit PB.
// LQ1 = true: lane qubit is the FIRST of the pair (basis 2*first+second).
template<int LBIT, int PB, bool LQ1>
__device__ __forceinline__ void conv_mx(float (&st)[32], const float4* __restrict__ U4, int lane) {
    constexpr int Lm = 1 << LBIT, mb = 1 << PB;
    const int a = (lane >> LBIT) & 1;
    float4 u0, u1;
    if (LQ1) { u0 = U4[2 * a]; u1 = U4[2 * a + 1]; }
    else     { u0 = U4[a];     u1 = U4[2 + a]; }
    float u00, u01, u02, u03, u10, u11, u12, u13;
    if (LQ1) {
        u00 = a ? u0.z : u0.x;  u01 = a ? u0.w : u0.y;
        u02 = a ? u0.x : u0.z;  u03 = a ? u0.y : u0.w;
        u10 = a ? u1.z : u1.x;  u11 = a ? u1.w : u1.y;
        u12 = a ? u1.x : u1.z;  u13 = a ? u1.y : u1.w;
    } else {
        u00 = a ? u0.y : u0.x;  u01 = a ? u0.w : u0.z;
        u02 = a ? u0.x : u0.y;  u03 = a ? u0.z : u0.w;
        u10 = a ? u1.y : u1.x;  u11 = a ? u1.w : u1.z;
        u12 = a ? u1.x : u1.y;  u13 = a ? u1.z : u1.w;
    }
    #pragma unroll
    for (int r0 = 0; r0 < 32; ++r0) if (!(r0 & mb)) {
        const int r1 = r0 | mb;
        float p0 = shx(st[r0], Lm), p1 = shx(st[r1], Lm);
        float o0 = st[r0], o1 = st[r1];
        st[r0] = fmaf(u00, o0, fmaf(u01, o1, fmaf(u02, p0, u03 * p1)));
        st[r1] = fmaf(u10, o0, fmaf(u11, o1, fmaf(u12, p0, u13 * p1)));
    }
}

__global__ __launch_bounds__(256, 4)
void qcnn_kernel(const float* __restrict__ x, const float* __restrict__ adj,
                 const float* __restrict__ w_proj, const float* __restrict__ b_proj,
                 const float* __restrict__ qp,
                 const float* __restrict__ w1, const float* __restrict__ b1,
                 const float* __restrict__ w2, const float* __restrict__ b2,
                 const float* __restrict__ w3, const float* __restrict__ b3,
                 float* __restrict__ out) {
    __shared__ alignas(16) float UUs[14][16];
    __shared__ float poolc[4], pools[4];
    __shared__ alignas(16) float w1s[512];         // w1 natural [64][8]
    __shared__ float4 w2p4[32 * 17];               // w2 rows padded to 68 floats
    __shared__ float4 h1buf4[CPB * 17];
    __shared__ float zbufR[CPB][8], zbufI[CPB][8];
    __shared__ float obuf[CPB];
    __shared__ float b1s[64], b2s[32], w3s[32];
    __shared__ float b3s;

    const int tid = threadIdx.x;

    // ---- build fused conv matrices U = C2 * G2 * C1 * G1 ----
    if (tid < 14) {
        const int layer = tid / 7, pi = tid - 7 * layer;
        const int base = layer * 28 + pi * 4;
        float c0, s0, c1, s1, c2, s2, c3, s3;
        sincosf(0.5f * qp[base + 0], &s0, &c0);
        sincosf(0.5f * qp[base + 1], &s1, &c1);
        sincosf(0.5f * qp[base + 2], &s2, &c2);
        sincosf(0.5f * qp[base + 3], &s3, &c3);
        float R0[2][2] = {{c0, -s0}, {s0, c0}};
        float R1[2][2] = {{c1, -s1}, {s1, c1}};
        float R2m[2][2] = {{c2, -s2}, {s2, c2}};
        float R3[2][2] = {{c3, -s3}, {s3, c3}};
        float A[4][4], G2m[4][4], Bm[4][4], Cm[4][4];
        #pragma unroll
        for (int ap = 0; ap < 2; ++ap)
        #pragma unroll
        for (int bp = 0; bp < 2; ++bp)
        #pragma unroll
        for (int aq = 0; aq < 2; ++aq)
        #pragma unroll
        for (int bq = 0; bq < 2; ++bq) {
            A[2 * ap + bp][2 * aq + bq]   = R0[ap][aq] * R1[bp][bq];
            G2m[2 * ap + bp][2 * aq + bq] = R2m[ap][aq] * R3[bp][bq];
        }
        const int sig1[4] = {0, 1, 3, 2};
        const int sig2[4] = {0, 3, 2, 1};
        #pragma unroll
        for (int xr = 0; xr < 4; ++xr)
            #pragma unroll
            for (int m = 0; m < 4; ++m) Bm[xr][m] = A[sig1[xr]][m];
        #pragma unroll
        for (int xr = 0; xr < 4; ++xr)
            #pragma unroll
            for (int m = 0; m < 4; ++m) {
                float acc = 0.f;
                #pragma unroll
                for (int y = 0; y < 4; ++y) acc = fmaf(G2m[xr][y], Bm[y][m], acc);
                Cm[xr][m] = acc;
            }
        #pragma unroll
        for (int xr = 0; xr < 4; ++xr)
            #pragma unroll
            for (int m = 0; m < 4; ++m) UUs[tid][xr * 4 + m] = Cm[sig2[xr]][m];
    }
    if (tid >= 16 && tid < 20) {
        float s, c;
        sincosf(0.5f * qp[56 + 2 * (tid - 16)], &s, &c);
        poolc[tid - 16] = c; pools[tid - 16] = s;
    }
    for (int i = tid; i < 512; i += 256) w1s[i] = w1[i];
    for (int i = tid; i < 2048; i += 256) {
        int row = i >> 6, j = i & 63;
        ((float*)w2p4)[row * 68 + j] = w2[i];
    }
    if (tid < 64) b1s[tid] = b1[tid];
    if (tid >= 64 && tid < 96) b2s[tid - 64] = b2[tid - 64];
    if (tid >= 96 && tid < 128) w3s[tid - 96] = w3[tid - 96];
    if (tid == 20) b3s = b3[0];
    __syncthreads();

    const int wid = tid >> 5;
    const int lane = tid & 31;
    const int comp = wid & 1;                 // 0 = re warp, 1 = im warp
    const int pairid = wid >> 1;              // 0..3
    const int ci = lane >> 3;                 // circuit-in-warp
    const int g = lane & 7;
    const int cb = pairid * 4 + ci;           // circuit-in-block 0..15
    const int cir = blockIdx.x * CPB + cb;
    const int b = cir / N_;
    const int n = cir - b * N_;

    // ---- angle projection: lane computes angle q = g of its circuit ----
    float av;
    {
        av = b_proj[g];
        const float* wrow = w_proj + g * (S_ * F_);
        const float* xb = x + (size_t)b * (S_ * N_ * F_) + n * F_;
        #pragma unroll
        for (int s = 0; s < S_; ++s) {
            float2 xv = *(const float2*)(xb + s * (N_ * F_));
            av = fmaf(wrow[2 * s], xv.x, av);
            av = fmaf(wrow[2 * s + 1], xv.y, av);
        }
        av = fminf(fmaxf(av, -PI_F), PI_F);
    }
    float sv, cv;
    sincosf(0.5f * av, &sv, &cv);
    float ch[8], sh[8];
    #pragma unroll
    for (int q = 0; q < 8; ++q) {
        ch[q] = __shfl_sync(FULL, cv, (lane & 24) | q);
        sh[q] = __shfl_sync(FULL, sv, (lane & 24) | q);
    }

    // ---- initial product state (this warp's component only) ----
    const int bq0 = (g >> 2) & 1, bq5 = (g >> 1) & 1, bq7 = g & 1;
    float magL = (bq0 ? sh[0] : ch[0]) * (bq5 ? sh[5] : ch[5]) * (bq7 ? sh[7] : ch[7]);
    const float sL = bq0 ? sh[4] : -sh[4];   // RZ(a4) on q0
    float ml[4];
    #pragma unroll
    for (int l = 0; l < 4; ++l)
        ml[l] = ((l >> 1) ? sh[4] : ch[4]) * ((l & 1) ? sh[6] : ch[6]);

    float st[32];
    #pragma unroll
    for (int t = 0; t < 8; ++t) {
        float s1 = (t & 4) ? sh[5] : -sh[5];
        float er = fmaf(ch[4], ch[5], -sL * s1);
        float ei = fmaf(ch[4], s1, sL * ch[5]);
        float s2 = (t & 2) ? sh[6] : -sh[6];
        float er2 = fmaf(er, ch[6], -ei * s2);
        float ei2 = fmaf(er, s2, ei * ch[6]);
        float s3 = (t & 1) ? sh[7] : -sh[7];
        float er3 = fmaf(er2, ch[7], -ei2 * s3);
        float ei3 = fmaf(er2, s3, ei2 * ch[7]);
        float m = magL * ((t & 4) ? sh[1] : ch[1]) * ((t & 2) ? sh[2] : ch[2])
                       * ((t & 1) ? sh[3] : ch[3]);
        const float tvt = m * (comp ? ei3 : er3);
        st[4 * t + 0] = tvt * ml[0];
        st[4 * t + 1] = tvt * ml[1];
        st[4 * t + 2] = tvt * ml[2];
        st[4 * t + 3] = tvt * ml[3];
    }

    // ---- graph CNOTs: composed conditional XOR permutation ----
    const int c = n & 7;
    const int pcq = (0x50612347u >> (4 * c)) & 0xF;    // posOf[c]
    int cond = (adj[c * N_ + g] > 0.f) && (g != c);
    const unsigned bal = __ballot_sync(FULL, cond);
    const unsigned mask8 = (bal >> (ci * 8)) & 0xFFu;
    constexpr int posOf[8] = {7, 4, 3, 2, 1, 6, 0, 5};
    int M = 0;
    #pragma unroll
    for (int t = 0; t < 8; ++t) M |= (int)((mask8 >> t) & 1u) << posOf[t];
    const int glm = (M >> 5) & 7;
    const int MR = M & 31;
    const int jbase = g << 5;
    // lane pass
    #pragma unroll
    for (int r = 0; r < 32; ++r) {
        const int bc = ((jbase | r) >> pcq) & 1;
        const int src = (lane & 24) | (bc ? (g ^ glm) : g);
        st[r] = __shfl_sync(FULL, st[r], src);
    }
    // register-bit passes (predicated swaps, pure ALU)
    #pragma unroll
    for (int t = 0; t < 5; ++t) {
        const int mt = 1 << t;
        const bool sw = (MR >> t) & 1;
        #pragma unroll
        for (int r0 = 0; r0 < 32; ++r0) if (!(r0 & mt)) {
            const int r1 = r0 | mt;
            const bool cnd = sw && (((jbase | r0) >> pcq) & 1);
            float t0 = st[r0], t1 = st[r1];
            st[r0] = cnd ? t1 : t0;  st[r1] = cnd ? t0 : t1;
        }
    }

    // ---- 2 conv layers ----
    #pragma unroll
    for (int l = 0; l < 2; ++l) {
        const float4* Ub = (const float4*)UUs[l * 7];
        conv_mx<2, 4, true>(st, Ub + 0 * 4, lane);    // (q0,q1)
        conv_rr<3, 2>(st, Ub + 1 * 4);                // (q2,q3)
        conv_mx<1, 1, false>(st, Ub + 2 * 4, lane);   // (q4,q5)
        conv_mx<0, 0, false>(st, Ub + 3 * 4, lane);   // (q6,q7)
        conv_rr<4, 3>(st, Ub + 4 * 4);                // (q1,q2)
        conv_rr<2, 1>(st, Ub + 5 * 4);                // (q3,q4)
        conv_mx<1, 0, true>(st, Ub + 6 * 4, lane);    // (q5,q6)
    }

    // ---- pooling RY on q0, q2, q4, q6 ----
    ry_lane<2>(st, poolc[0], pools[0], lane);  // q0 (lane bit 2)
    ry_reg<3>(st, poolc[1], pools[1]);         // q2
    ry_reg<1>(st, poolc[2], pools[2]);         // q4
    ry_reg<0>(st, poolc[3], pools[3]);         // q6

    // ---- partial <Z_w> from this component ----
    float tot = 0.f, z1 = 0.f, z2 = 0.f, z3 = 0.f, z4 = 0.f, z6 = 0.f;
    #pragma unroll
    for (int r = 0; r < 32; ++r) {
        float p = st[r] * st[r];
        tot += p;
        z1 += ((r >> 4) & 1) ? -p : p;
        z2 += ((r >> 3) & 1) ? -p : p;
        z3 += ((r >> 2) & 1) ? -p : p;
        z4 += ((r >> 1) & 1) ? -p : p;
        z6 += (r & 1) ? -p : p;
    }
    float z[8];
    z[0] = bq0 ? -tot : tot;
    z[5] = bq5 ? -tot : tot;
    z[7] = bq7 ? -tot : tot;
    z[1] = z1; z[2] = z2; z[3] = z3; z[4] = z4; z[6] = z6;
    #pragma unroll
    for (int off = 1; off < 8; off <<= 1) {
        #pragma unroll
        for (int w = 0; w < 8; ++w) z[w] += shx(z[w], off);
    }

    // ---- exchange partial z between the component warps ----
    if (comp) zbufI[cb][g] = z[g];
    else      zbufR[cb][g] = z[g];
    __syncthreads();
    {
        const float* zo = comp ? zbufR[cb] : zbufI[cb];
        #pragma unroll
        for (int w = 0; w < 8; ++w) z[w] += zo[w];
    }

    // ---- MLP head, split across the warp pair ----
    // h1: re warp computes rows [0,32), im warp rows [32,64); 4 rows per lane.
    const int rbase = comp * 32 + 4 * g;
    float h1v[4];
    #pragma unroll
    for (int i = 0; i < 4; ++i) {
        const int row = rbase + i;
        float4 wa = *(const float4*)(w1s + row * 8);
        float4 wb = *(const float4*)(w1s + row * 8 + 4);
        float acc = b1s[row];
        acc = fmaf(wa.x, z[0], acc); acc = fmaf(wa.y, z[1], acc);
        acc = fmaf(wa.z, z[2], acc); acc = fmaf(wa.w, z[3], acc);
        acc = fmaf(wb.x, z[4], acc); acc = fmaf(wb.y, z[5], acc);
        acc = fmaf(wb.z, z[6], acc); acc = fmaf(wb.w, z[7], acc);
        h1v[i] = fmaxf(acc, 0.f);
    }
    *(float4*)((float*)h1buf4 + cb * 68 + rbase) =
        make_float4(h1v[0], h1v[1], h1v[2], h1v[3]);
    __syncthreads();

    // h2: re warp rows {g, g+8}, im warp rows {g+16, g+24}
    const int hrow = g + comp * 16;
    float acc2a = b2s[hrow], acc2b = b2s[hrow + 8];
    const float4* h1p = h1buf4 + cb * 17;
    #pragma unroll
    for (int j4 = 0; j4 < 16; ++j4) {
        float4 h = h1p[j4];
        float4 wa = w2p4[hrow * 17 + j4];
        float4 wb = w2p4[(hrow + 8) * 17 + j4];
        acc2a = fmaf(wa.x, h.x, fmaf(wa.y, h.y, fmaf(wa.z, h.z, fmaf(wa.w, h.w, acc2a))));
        acc2b = fmaf(wb.x, h.x, fmaf(wb.y, h.y, fmaf(wb.z, h.z, fmaf(wb.w, h.w, acc2b))));
    }
    float o = fmaf(w3s[hrow], fmaxf(acc2a, 0.f), w3s[hrow + 8] * fmaxf(acc2b, 0.f));
    o += shx(o, 1); o += shx(o, 2); o += shx(o, 4);
    if (comp && g == 0) obuf[cb] = o;
    __syncthreads();
    if (!comp && g == 0) out[cir] = o + obuf[cb] + b3s;
}

extern "C" void kernel_launch(void* const* d_in, const int* in_sizes, int n_in,
                              void* d_out, int out_size) {
    const float* x      = (const float*)d_in[0];
    const float* adj    = (const float*)d_in[1];
    const float* w_proj = (const float*)d_in[2];
    const float* b_proj = (const float*)d_in[3];
    const float* qp     = (const float*)d_in[4];
    const float* w1     = (const float*)d_in[5];
    const float* b1     = (const float*)d_in[6];
    const float* w2     = (const float*)d_in[7];
    const float* b2     = (const float*)d_in[8];
    const float* w3     = (const float*)d_in[9];
    const float* b3     = (const float*)d_in[10];
    float* out = (float*)d_out;

    const int blocks = NCIRC / CPB;   // 828
    qcnn_kernel<<<blocks, 256>>>(x, adj, w_proj, b_proj, qp,
                                 w1, b1, w2, b2, w3, b3, out);
}

// round 9
// speedup vs baseline: 1.0433x; 1.0433x over previous
#include <cuda_runtime.h>

#define FULL 0xffffffffu
typedef unsigned long long u64;

static constexpr int B_ = 64;
static constexpr int S_ = 12;
static constexpr int N_ = 207;
static constexpr int F_ = 2;
static constexpr int NCIRC = B_ * N_;       // 13248
static constexpr int CPB = 16;              // circuits per 256-thread block
static constexpr float PI_F = 3.14159265358979323846f;

// Each warp-PAIR handles 4 circuits: even warp = re component, odd warp = im.
// Within a warp: 4 groups of 8 lanes, one circuit per group.
// Flat j (8 bits) = (g << 5) | (k << 1) | h;  g = lane & 7, k = pack idx (4 bits),
// h = intra-pack half (bit0).
// qubit -> j-bit: q0->7 q5->6 q7->5 (lane g bits 2,1,0)
//                 q1->4 q2->3 q3->2 q4->1 (k bits 3..0)   q6->0 (intra-pack)
// State: u64 st2[16]; st2[k] packs (h=0, h=1) as (lo, hi) fp32.

__device__ __forceinline__ float shx(float v, int m) { return __shfl_xor_sync(FULL, v, m); }

__device__ __forceinline__ u64 pk2(float lo, float hi) {
    u64 r;
    asm("mov.b64 %0, {%1, %2};" : "=l"(r) : "r"(__float_as_uint(lo)), "r"(__float_as_uint(hi)));
    return r;
}
__device__ __forceinline__ void unpk(u64 v, float& lo, float& hi) {
    unsigned a, b;
    asm("mov.b64 {%0, %1}, %2;" : "=r"(a), "=r"(b) : "l"(v));
    lo = __uint_as_float(a); hi = __uint_as_float(b);
}
__device__ __forceinline__ u64 bc2(float x) { return pk2(x, x); }
__device__ __forceinline__ u64 f2fma(u64 a, u64 b, u64 c) {
    u64 d;
    asm("fma.rn.f32x2 %0, %1, %2, %3;" : "=l"(d) : "l"(a), "l"(b), "l"(c));
    return d;
}
__device__ __forceinline__ u64 f2mul(u64 a, u64 b) {
    u64 d;
    asm("mul.rn.f32x2 %0, %1, %2;" : "=l"(d) : "l"(a), "l"(b));
    return d;
}
__device__ __forceinline__ u64 swp2(u64 v) { float a, b; unpk(v, a, b); return pk2(b, a); }
__device__ __forceinline__ u64 shx2(u64 v, int m) {
    float a, b; unpk(v, a, b);
    return pk2(shx(a, m), shx(b, m));
}

// ---- packed RY on k-bit P ----
template<int P>
__device__ __forceinline__ void ry_reg2(u64 (&st)[16], u64 cc, u64 ss, u64 ns) {
    constexpr int m = 1 << P;
    #pragma unroll
    for (int r = 0; r < 16; ++r) if (!(r & m)) {
        const int r1 = r | m;
        u64 a0 = st[r], a1 = st[r1];
        st[r]  = f2fma(cc, a0, f2mul(ns, a1));
        st[r1] = f2fma(ss, a0, f2mul(cc, a1));
    }
}

// ---- packed RY on intra-pack bit (q6) ----
__device__ __forceinline__ void ry_intra(u64 (&st)[16], float c, float s) {
    const u64 cc = bc2(c), sn = pk2(-s, s);
    #pragma unroll
    for (int k = 0; k < 16; ++k) {
        u64 v = st[k];
        st[k] = f2fma(cc, v, f2mul(sn, swp2(v)));
    }
}

// ---- packed RY on lane bit LB ----
template<int LB>
__device__ __forceinline__ void ry_lane2(u64 (&st)[16], float c, float s, int lane) {
    constexpr int L = 1 << LB;
    const u64 cc = bc2(c);
    const u64 sg = bc2(((lane >> LB) & 1) ? s : -s);
    #pragma unroll
    for (int k = 0; k < 16; ++k) {
        u64 p = shx2(st[k], L);
        st[k] = f2fma(cc, st[k], f2mul(sg, p));
    }
}

// ---- packed fused conv pair, both qubits on k-bits (KA first, KB second) ----
template<int KA, int KB>
__device__ __forceinline__ void conv_rr2(u64 (&st)[16], const u64* __restrict__ U) {
    u64 u[16];
    #pragma unroll
    for (int i = 0; i < 8; ++i) {
        ulonglong2 t = ((const ulonglong2*)U)[i];
        u[2 * i] = t.x; u[2 * i + 1] = t.y;
    }
    constexpr int ma = 1 << KA, mb = 1 << KB;
    #pragma unroll
    for (int k = 0; k < 16; ++k) if (!(k & (ma | mb))) {
        const int i1 = k | mb, i2 = k | ma, i3 = k | ma | mb;
        u64 v0 = st[k], v1 = st[i1], v2 = st[i2], v3 = st[i3];
        st[k]  = f2fma(u[0],  v0, f2fma(u[1],  v1, f2fma(u[2],  v2, f2mul(u[3],  v3))));
        st[i1] = f2fma(u[4],  v0, f2fma(u[5],  v1, f2fma(u[6],  v2, f2mul(u[7],  v3))));
        st[i2] = f2fma(u[8],  v0, f2fma(u[9],  v1, f2fma(u[10], v2, f2mul(u[11], v3))));
        st[i3] = f2fma(u[12], v0, f2fma(u[13], v1, f2fma(u[14], v2, f2mul(u[15], v3))));
    }
}

// ---- packed fused conv pair, one qubit on lane bit LBIT, one on k-bit KB ----
// LQ1 = true: lane qubit is FIRST of the pair (basis 2*first+second).
template<int LBIT, int KB, bool LQ1>
__device__ __forceinline__ void conv_mx2(u64 (&st)[16], const u64* __restrict__ U, int lane) {
    constexpr int Lm = 1 << LBIT, mb = 1 << KB;
    const int a = (lane >> LBIT) & 1;
    int r0, r1, c0, c1, d0, d1;
    if (LQ1) { r0 = 2 * a; r1 = 2 * a + 1; c0 = 2 * a; c1 = 2 * a + 1; d0 = 2 * a ^ 2; d1 = (2 * a ^ 2) + 1; }
    else     { r0 = a;     r1 = 2 + a;     c0 = a;     c1 = 2 + a;     d0 = a ^ 1;     d1 = 2 + (a ^ 1); }
    const u64 u00 = U[r0 * 4 + c0], u01 = U[r0 * 4 + c1], u02 = U[r0 * 4 + d0], u03 = U[r0 * 4 + d1];
    const u64 u10 = U[r1 * 4 + c0], u11 = U[r1 * 4 + c1], u12 = U[r1 * 4 + d0], u13 = U[r1 * 4 + d1];
    #pragma unroll
    for (int k = 0; k < 16; ++k) if (!(k & mb)) {
        const int k1 = k | mb;
        u64 p0 = shx2(st[k], Lm), p1 = shx2(st[k1], Lm);
        u64 o0 = st[k], o1 = st[k1];
        st[k]  = f2fma(u00, o0, f2fma(u01, o1, f2fma(u02, p0, f2mul(u03, p1))));
        st[k1] = f2fma(u10, o0, f2fma(u11, o1, f2fma(u12, p0, f2mul(u13, p1))));
    }
}

// ---- packed fused conv pair with the intra-pack qubit (q6) + a lane qubit ----
// x,y: basis rows/cols of (lo,hi) own states; X: partner column XOR; Lmask: lane xor.
__device__ __forceinline__ void conv_intra(u64 (&st)[16], const float* __restrict__ Us,
                                           int x, int y, int X, int Lmask) {
    const u64 a2 = pk2(Us[x * 4 + x],       Us[y * 4 + y]);
    const u64 b2 = pk2(Us[x * 4 + y],       Us[y * 4 + x]);
    const u64 c2 = pk2(Us[x * 4 + (x ^ X)], Us[y * 4 + (y ^ X)]);
    const u64 d2 = pk2(Us[x * 4 + (y ^ X)], Us[y * 4 + (x ^ X)]);
    #pragma unroll
    for (int k = 0; k < 16; ++k) {
        u64 v = st[k];
        float vl, vh; unpk(v, vl, vh);
        float pl = shx(vl, Lmask), ph = shx(vh, Lmask);
        u64 p = pk2(pl, ph), psw = pk2(ph, pl), vsw = pk2(vh, vl);
        st[k] = f2fma(a2, v, f2fma(b2, vsw, f2fma(c2, p, f2mul(d2, psw))));
    }
}

__global__ __launch_bounds__(256, 3)
void qcnn_kernel(const float* __restrict__ x, const float* __restrict__ adj,
                 const float* __restrict__ w_proj, const float* __restrict__ b_proj,
                 const float* __restrict__ qp,
                 const float* __restrict__ w1, const float* __restrict__ b1,
                 const float* __restrict__ w2, const float* __restrict__ b2,
                 const float* __restrict__ w3, const float* __restrict__ b3,
                 float* __restrict__ out) {
    __shared__ alignas(16) float UUs[14][16];      // scalar fused conv matrices
    __shared__ alignas(16) u64 UU2[14][16];        // (u,u) packed duplicates
    __shared__ float poolc[4], pools[4];
    __shared__ alignas(16) float w1s[512];         // w1 natural [64][8]
    __shared__ float4 w2p4[32 * 17];               // w2 rows padded to 68 floats
    __shared__ float4 h1buf4[CPB * 17];
    __shared__ float zbuf[CPB][8];                 // im-warp partial z
    __shared__ float b1s[64], b2s[32], w3s[32];
    __shared__ float b3s;

    const int tid = threadIdx.x;

    // ---- build fused conv matrices U = C2 * G2 * C1 * G1 ----
    if (tid < 14) {
        const int layer = tid / 7, pi = tid - 7 * layer;
        const int base = layer * 28 + pi * 4;
        float c0, s0, c1, s1, c2, s2, c3, s3;
        sincosf(0.5f * qp[base + 0], &s0, &c0);
        sincosf(0.5f * qp[base + 1], &s1, &c1);
        sincosf(0.5f * qp[base + 2], &s2, &c2);
        sincosf(0.5f * qp[base + 3], &s3, &c3);
        float R0[2][2] = {{c0, -s0}, {s0, c0}};
        float R1[2][2] = {{c1, -s1}, {s1, c1}};
        float R2m[2][2] = {{c2, -s2}, {s2, c2}};
        float R3[2][2] = {{c3, -s3}, {s3, c3}};
        float A[4][4], G2m[4][4], Bm[4][4], Cm[4][4];
        #pragma unroll
        for (int ap = 0; ap < 2; ++ap)
        #pragma unroll
        for (int bp = 0; bp < 2; ++bp)
        #pragma unroll
        for (int aq = 0; aq < 2; ++aq)
        #pragma unroll
        for (int bq = 0; bq < 2; ++bq) {
            A[2 * ap + bp][2 * aq + bq]   = R0[ap][aq] * R1[bp][bq];
            G2m[2 * ap + bp][2 * aq + bq] = R2m[ap][aq] * R3[bp][bq];
        }
        const int sig1[4] = {0, 1, 3, 2};
        const int sig2[4] = {0, 3, 2, 1};
        #pragma unroll
        for (int xr = 0; xr < 4; ++xr)
            #pragma unroll
            for (int m = 0; m < 4; ++m) Bm[xr][m] = A[sig1[xr]][m];
        #pragma unroll
        for (int xr = 0; xr < 4; ++xr)
            #pragma unroll
            for (int m = 0; m < 4; ++m) {
                float acc = 0.f;
                #pragma unroll
                for (int y = 0; y < 4; ++y) acc = fmaf(G2m[xr][y], Bm[y][m], acc);
                Cm[xr][m] = acc;
            }
        #pragma unroll
        for (int xr = 0; xr < 4; ++xr)
            #pragma unroll
            for (int m = 0; m < 4; ++m) {
                float u = Cm[sig2[xr]][m];
                UUs[tid][xr * 4 + m] = u;
                UU2[tid][xr * 4 + m] = pk2(u, u);
            }
    }
    if (tid >= 16 && tid < 20) {
        float s, c;
        sincosf(0.5f * qp[56 + 2 * (tid - 16)], &s, &c);
        poolc[tid - 16] = c; pools[tid - 16] = s;
    }
    for (int i = tid; i < 512; i += 256) w1s[i] = w1[i];
    for (int i = tid; i < 2048; i += 256) {
        int row = i >> 6, j = i & 63;
        ((float*)w2p4)[row * 68 + j] = w2[i];
    }
    if (tid < 64) b1s[tid] = b1[tid];
    if (tid >= 64 && tid < 96) b2s[tid - 64] = b2[tid - 64];
    if (tid >= 96 && tid < 128) w3s[tid - 96] = w3[tid - 96];
    if (tid == 20) b3s = b3[0];
    __syncthreads();

    const int wid = tid >> 5;
    const int lane = tid & 31;
    const int comp = wid & 1;                 // 0 = re warp, 1 = im warp
    const int pairid = wid >> 1;              // 0..3
    const int ci = lane >> 3;                 // circuit-in-warp
    const int g = lane & 7;
    const int cb = pairid * 4 + ci;           // circuit-in-block 0..15
    const int cir = blockIdx.x * CPB + cb;
    const int b = cir / N_;
    const int n = cir - b * N_;

    // ---- angle projection: lane computes angle q = g of its circuit ----
    float av;
    {
        av = b_proj[g];
        const float* wrow = w_proj + g * (S_ * F_);
        const float* xb = x + (size_t)b * (S_ * N_ * F_) + n * F_;
        #pragma unroll
        for (int s = 0; s < S_; ++s) {
            float2 xv = *(const float2*)(xb + s * (N_ * F_));
            av = fmaf(wrow[2 * s], xv.x, av);
            av = fmaf(wrow[2 * s + 1], xv.y, av);
        }
        av = fminf(fmaxf(av, -PI_F), PI_F);
    }
    float sv, cv;
    sincosf(0.5f * av, &sv, &cv);
    float ch[8], sh[8];
    #pragma unroll
    for (int q = 0; q < 8; ++q) {
        ch[q] = __shfl_sync(FULL, cv, (lane & 24) | q);
        sh[q] = __shfl_sync(FULL, sv, (lane & 24) | q);
    }

    // ---- initial product state (this warp's component only), packed ----
    const int bq0 = (g >> 2) & 1, bq5 = (g >> 1) & 1, bq7 = g & 1;
    float magL = (bq0 ? sh[0] : ch[0]) * (bq5 ? sh[5] : ch[5]) * (bq7 ? sh[7] : ch[7]);
    const float sL = bq0 ? sh[4] : -sh[4];   // RZ(a4) on q0
    // ml2[q4bit] packs (q6=0, q6=1) magnitude factors
    u64 ml2[2];
    ml2[0] = pk2(ch[4] * ch[6], ch[4] * sh[6]);
    ml2[1] = pk2(sh[4] * ch[6], sh[4] * sh[6]);

    u64 st2[16];
    #pragma unroll
    for (int t = 0; t < 8; ++t) {
        float s1 = (t & 4) ? sh[5] : -sh[5];
        float er = fmaf(ch[4], ch[5], -sL * s1);
        float ei = fmaf(ch[4], s1, sL * ch[5]);
        float s2 = (t & 2) ? sh[6] : -sh[6];
        float er2 = fmaf(er, ch[6], -ei * s2);
        float ei2 = fmaf(er, s2, ei * ch[6]);
        float s3 = (t & 1) ? sh[7] : -sh[7];
        float er3 = fmaf(er2, ch[7], -ei2 * s3);
        float ei3 = fmaf(er2, s3, ei2 * ch[7]);
        float m = magL * ((t & 4) ? sh[1] : ch[1]) * ((t & 2) ? sh[2] : ch[2])
                       * ((t & 1) ? sh[3] : ch[3]);
        const u64 tp = bc2(m * (comp ? ei3 : er3));
        st2[2 * t + 0] = f2mul(tp, ml2[0]);
        st2[2 * t + 1] = f2mul(tp, ml2[1]);
    }

    // ---- graph CNOTs: composed conditional XOR permutation (branch-free) ----
    const int c = n & 7;
    const int pcq = (0x50612347u >> (4 * c)) & 0xF;    // posOf[c]
    int cond = (adj[c * N_ + g] > 0.f) && (g != c);
    const unsigned bal = __ballot_sync(FULL, cond);
    const unsigned mask8 = (bal >> (ci * 8)) & 0xFFu;
    constexpr int posOf[8] = {7, 4, 3, 2, 1, 6, 0, 5};
    int M = 0;
    #pragma unroll
    for (int t = 0; t < 8; ++t) M |= (int)((mask8 >> t) & 1u) << posOf[t];
    const int glm = (M >> 5) & 7;
    const int kkm = (M >> 1) & 15;
    const int hm  = M & 1;
    // lane pass (per-half control bits handle pcq==0 too)
    #pragma unroll
    for (int k = 0; k < 16; ++k) {
        const int jb = (g << 5) | (k << 1);
        const int bcL = (jb >> pcq) & 1;
        const int bcH = ((jb | 1) >> pcq) & 1;
        const int srcL = (lane & 24) | (bcL ? (g ^ glm) : g);
        const int srcH = (lane & 24) | (bcH ? (g ^ glm) : g);
        float l_, h_; unpk(st2[k], l_, h_);
        st2[k] = pk2(__shfl_sync(FULL, l_, srcL), __shfl_sync(FULL, h_, srcH));
    }
    // k-bit passes (predicated per-half swaps)
    #pragma unroll
    for (int t = 0; t < 4; ++t) {
        const int mt = 1 << t;
        const bool sw = (kkm >> t) & 1;
        #pragma unroll
        for (int r0 = 0; r0 < 16; ++r0) if (!(r0 & mt)) {
            const int r1 = r0 | mt;
            const int jb = (g << 5) | (r0 << 1);
            const bool cL = sw && ((jb >> pcq) & 1);
            const bool cH = sw && (((jb | 1) >> pcq) & 1);
            float l0, h0, l1, h1;
            unpk(st2[r0], l0, h0); unpk(st2[r1], l1, h1);
            st2[r0] = pk2(cL ? l1 : l0, cH ? h1 : h0);
            st2[r1] = pk2(cL ? l0 : l1, cH ? h0 : h1);
        }
    }
    // intra pass (q6 target); no-op when hm==0
    #pragma unroll
    for (int k = 0; k < 16; ++k) {
        const int jb = (g << 5) | (k << 1);
        const bool cL = hm && ((jb >> pcq) & 1);
        const bool cH = hm && (((jb | 1) >> pcq) & 1);
        float l_, h_; unpk(st2[k], l_, h_);
        st2[k] = pk2(cL ? h_ : l_, cH ? l_ : h_);
    }

    // ---- 2 conv layers (packed) ----
    #pragma unroll
    for (int l = 0; l < 2; ++l) {
        const u64* U2b = &UU2[l * 7][0];
        const float* Ufb = &UUs[l * 7][0];
        conv_mx2<2, 3, true>(st2, U2b + 0 * 16, lane);                   // (q0,q1)
        conv_rr2<2, 1>(st2, U2b + 1 * 16);                               // (q2,q3)
        conv_mx2<1, 0, false>(st2, U2b + 2 * 16, lane);                  // (q4,q5)
        conv_intra(st2, Ufb + 3 * 16, bq7, 2 + bq7, 1, 1);               // (q6,q7)
        conv_rr2<3, 2>(st2, U2b + 4 * 16);                               // (q1,q2)
        conv_rr2<1, 0>(st2, U2b + 5 * 16);                               // (q3,q4)
        conv_intra(st2, Ufb + 6 * 16, 2 * bq5, 2 * bq5 + 1, 2, 2);       // (q5,q6)
    }

    // ---- pooling RY on q0, q2, q4, q6 ----
    ry_lane2<2>(st2, poolc[0], pools[0], lane);                          // q0
    {
        const u64 cc = bc2(poolc[1]), ss = bc2(pools[1]), ns = bc2(-pools[1]);
        ry_reg2<2>(st2, cc, ss, ns);                                     // q2 (k-bit2)
    }
    {
        const u64 cc = bc2(poolc[2]), ss = bc2(pools[2]), ns = bc2(-pools[2]);
        ry_reg2<0>(st2, cc, ss, ns);                                     // q4 (k-bit0)
    }
    ry_intra(st2, poolc[3], pools[3]);                                   // q6

    // ---- partial <Z_w> from this component (packed accumulate) ----
    const u64 pone = bc2(1.f), mone = bc2(-1.f);
    u64 t2 = 0, a1 = 0, a2 = 0, a3 = 0, a4 = 0;
    #pragma unroll
    for (int k = 0; k < 16; ++k) {
        u64 p2 = f2mul(st2[k], st2[k]);
        t2 = f2fma(p2, pone, t2);
        a1 = f2fma(p2, (k & 8) ? mone : pone, a1);
        a2 = f2fma(p2, (k & 4) ? mone : pone, a2);
        a3 = f2fma(p2, (k & 2) ? mone : pone, a3);
        a4 = f2fma(p2, (k & 1) ? mone : pone, a4);
    }
    float z[8];
    {
        float tl, th; unpk(t2, tl, th);
        const float tot = tl + th;
        z[6] = tl - th;
        z[0] = bq0 ? -tot : tot;
        z[5] = bq5 ? -tot : tot;
        z[7] = bq7 ? -tot : tot;
        float xl, xh;
        unpk(a1, xl, xh); z[1] = xl + xh;
        unpk(a2, xl, xh); z[2] = xl + xh;
        unpk(a3, xl, xh); z[3] = xl + xh;
        unpk(a4, xl, xh); z[4] = xl + xh;
    }
    #pragma unroll
    for (int off = 1; off < 8; off <<= 1) {
        #pragma unroll
        for (int w = 0; w < 8; ++w) z[w] += shx(z[w], off);
    }

    // im warp publishes its partial z; re warp combines and runs the MLP
    if (comp) zbuf[cb][g] = z[g];
    __syncthreads();

    if (!comp) {
        #pragma unroll
        for (int w = 0; w < 8; ++w) z[w] += zbuf[cb][w];

        // ---- MLP head: 8 -> 64 -> 32 -> 1 ----
        float h1v[8];
        const float* w1row = w1s + g * 64;
        #pragma unroll
        for (int i = 0; i < 8; ++i) {
            float4 wa = *(const float4*)(w1row + i * 8);
            float4 wb = *(const float4*)(w1row + i * 8 + 4);
            float acc = b1s[8 * g + i];
            acc = fmaf(wa.x, z[0], acc); acc = fmaf(wa.y, z[1], acc);
            acc = fmaf(wa.z, z[2], acc); acc = fmaf(wa.w, z[3], acc);
            acc = fmaf(wb.x, z[4], acc); acc = fmaf(wb.y, z[5], acc);
            acc = fmaf(wb.z, z[6], acc); acc = fmaf(wb.w, z[7], acc);
            h1v[i] = fmaxf(acc, 0.f);
        }
        {
            float4* dst = (float4*)((float*)h1buf4 + cb * 68 + 8 * g);
            dst[0] = make_float4(h1v[0], h1v[1], h1v[2], h1v[3]);
            dst[1] = make_float4(h1v[4], h1v[5], h1v[6], h1v[7]);
        }
        __syncwarp();

        // h2: this lane computes rows g, g+8, g+16, g+24
        float acc2[4];
        #pragma unroll
        for (int i = 0; i < 4; ++i) acc2[i] = b2s[g + 8 * i];
        const float4* h1p = h1buf4 + cb * 17;
        #pragma unroll
        for (int j4 = 0; j4 < 16; ++j4) {
            float4 h = h1p[j4];
            #pragma unroll
            for (int i = 0; i < 4; ++i) {
                float4 w = w2p4[(g + 8 * i) * 17 + j4];
                acc2[i] = fmaf(w.x, h.x, fmaf(w.y, h.y, fmaf(w.z, h.z, fmaf(w.w, h.w, acc2[i]))));
            }
        }
        float o = 0.f;
        #pragma unroll
        for (int i = 0; i < 4; ++i)
            o = fmaf(w3s[g + 8 * i], fmaxf(acc2[i], 0.f), o);
        o += shx(o, 1); o += shx(o, 2); o += shx(o, 4);
        if (g == 0) out[cir] = o + b3s;
    }
}

extern "C" void kernel_launch(void* const* d_in, const int* in_sizes, int n_in,
                              void* d_out, int out_size) {
    const float* x      = (const float*)d_in[0];
    const float* adj    = (const float*)d_in[1];
    const float* w_proj = (const float*)d_in[2];
    const float* b_proj = (const float*)d_in[3];
    const float* qp     = (const float*)d_in[4];
    const float* w1     = (const float*)d_in[5];
    const float* b1     = (const float*)d_in[6];
    const float* w2     = (const float*)d_in[7];
    const float* b2     = (const float*)d_in[8];
    const float* w3     = (const float*)d_in[9];
    const float* b3     = (const float*)d_in[10];
    float* out = (float*)d_out;

    const int blocks = NCIRC / CPB;   // 828
    qcnn_kernel<<<blocks, 256>>>(x, adj, w_proj, b_proj, qp,
                                 w1, b1, w2, b2, w3, b3, out);
}